// round 7
// baseline (speedup 1.0000x reference)
#include <cuda_runtime.h>
#include <math.h>

#define N_PTS 16384            // 2*8192 points, both batches flattened
#define KNN 5
#define NC 32                  // cells per axis (3D)
#define NCELLS (NC * NC * NC)  // 32768
#define XMIN (-4.5f)
#define W (9.0f / NC)          // 0.28125
#define INV_W (NC / 9.0f)

#define MAIN_THREADS 128
#define MAIN_WARPS (MAIN_THREADS / 32)            // 4
#define SRC_PER_WARP 4
#define SRC_PER_BLOCK (MAIN_WARPS * SRC_PER_WARP) // 16
#define MAIN_BLOCKS (N_PTS / SRC_PER_BLOCK)       // 1024

// ---- scratch (zero-initialized at module load; finalize re-zeroes hists) ----
__device__ float4 g_tsort[N_PTS];   // (-2x,-2y,-2z,t^2) cell-ordered (linear z,y,x)
__device__ float4 g_ssort[N_PTS];   // (x,y,z, valid? s2 : -1) Morton-cell-ordered
__device__ int    g_thist[NCELLS];
__device__ int    g_shist[NCELLS];
__device__ int    g_tstart[NCELLS + 1];
__device__ int    g_tcur[NCELLS];
__device__ int    g_scur[NCELLS];
__device__ float  g_bsum[MAIN_BLOCKS];
__device__ int    g_bcnt[MAIN_BLOCKS];

__device__ __forceinline__ int cell_coord(float v) {
    int c = (int)floorf((v - XMIN) * INV_W);
    return min(NC - 1, max(0, c));
}

__device__ __forceinline__ unsigned part1by2(unsigned v) {
    v &= 0x3FF;
    v = (v | (v << 16)) & 0x030000FF;
    v = (v | (v << 8))  & 0x0300F00F;
    v = (v | (v << 4))  & 0x030C30C3;
    v = (v | (v << 2))  & 0x09249249;
    return v;
}
__device__ __forceinline__ int morton3(int cx, int cy, int cz) {
    return (int)(part1by2(cx) | (part1by2(cy) << 1) | (part1by2(cz) << 2));
}

// ---------------------------------------------------------------------------
__global__ void hist_kernel(const float* __restrict__ src,
                            const float* __restrict__ tgt) {
    int gid = blockIdx.x * blockDim.x + threadIdx.x;   // 0..32767
    if (gid < N_PTS) {
        int cx = cell_coord(tgt[3 * gid]);
        int cy = cell_coord(tgt[3 * gid + 1]);
        int cz = cell_coord(tgt[3 * gid + 2]);
        atomicAdd(&g_thist[(cz * NC + cy) * NC + cx], 1);
    } else {
        int i = gid - N_PTS;
        int cx = cell_coord(src[3 * i]);
        int cy = cell_coord(src[3 * i + 1]);
        int cz = cell_coord(src[3 * i + 2]);
        atomicAdd(&g_shist[morton3(cx, cy, cz)], 1);
    }
}

// ---------------------------------------------------------------------------
// scan: exclusive scan of both 32768-cell histograms. 1 block, 1024 threads,
// 32 cells per thread. Two global passes (sum, then offsets) to keep register
// usage low (the R6 register-array version exceeded the per-block reg file).
// ---------------------------------------------------------------------------
#define CELLS_PER_T (NCELLS / 1024)   // 32
__global__ __launch_bounds__(1024) void scan_kernel() {
    __shared__ int pt[1024], ps[1024];
    const int tid = threadIdx.x;
    const int c0 = tid * CELLS_PER_T;
    int tsum = 0, ssum = 0;
    for (int j = 0; j < CELLS_PER_T; ++j) {
        tsum += g_thist[c0 + j];
        ssum += g_shist[c0 + j];
    }
    pt[tid] = tsum; ps[tid] = ssum;
    __syncthreads();
    for (int off = 1; off < 1024; off <<= 1) {
        int ta = (tid >= off) ? pt[tid - off] : 0;
        int sa = (tid >= off) ? ps[tid - off] : 0;
        __syncthreads();
        pt[tid] += ta; ps[tid] += sa;
        __syncthreads();
    }
    int trun = pt[tid] - tsum;   // exclusive offsets
    int srun = ps[tid] - ssum;
    for (int j = 0; j < CELLS_PER_T; ++j) {
        int c = c0 + j;
        int tv = g_thist[c], sv = g_shist[c];
        g_tstart[c] = trun; g_tcur[c] = trun; trun += tv;
        g_scur[c] = srun;                     srun += sv;
    }
    if (tid == 1023) g_tstart[NCELLS] = N_PTS;
}

// ---------------------------------------------------------------------------
__global__ void scatter_kernel(const float* __restrict__ src,
                               const float* __restrict__ tgt) {
    int gid = blockIdx.x * blockDim.x + threadIdx.x;
    if (gid < N_PTS) {
        float x = tgt[3 * gid], y = tgt[3 * gid + 1], z = tgt[3 * gid + 2];
        bool valid = (x != 0.0f) || (y != 0.0f) || (z != 0.0f);
        float t2 = fmaf(x, x, fmaf(y, y, z * z));
        float4 v;
        if (valid) { v.x = -2.0f * x; v.y = -2.0f * y; v.z = -2.0f * z; v.w = t2; }
        else       { v.x = 0.0f;      v.y = 0.0f;      v.z = 0.0f;      v.w = 1e30f; }
        int c = (cell_coord(z) * NC + cell_coord(y)) * NC + cell_coord(x);
        g_tsort[atomicAdd(&g_tcur[c], 1)] = v;
    } else {
        int i = gid - N_PTS;
        float x = src[3 * i], y = src[3 * i + 1], z = src[3 * i + 2];
        bool valid = (x != 0.0f) || (y != 0.0f) || (z != 0.0f);
        float s2 = fmaf(x, x, fmaf(y, y, z * z));
        float4 v; v.x = x; v.y = y; v.z = z; v.w = valid ? s2 : -1.0f;
        int c = morton3(cell_coord(x), cell_coord(y), cell_coord(z));
        g_ssort[atomicAdd(&g_scur[c], 1)] = v;
    }
}

// Branchless sorted insert, ascending m0..m4 (exact no-op when q >= m4).
__device__ __forceinline__ void insert5(float q, float& m0, float& m1,
                                        float& m2, float& m3, float& m4) {
    float t0 = fminf(m0, q);
    float t1 = fminf(m1, fmaxf(m0, q));
    float t2 = fminf(m2, fmaxf(m1, q));
    float t3 = fminf(m3, fmaxf(m2, q));
    float t4 = fminf(m4, fmaxf(m3, q));
    m0 = t0; m1 = t1; m2 = t2; m3 = t3; m4 = t4;
}

// Warp butterfly merge of 32 per-lane ascending-5 lists -> exact union top-5
// sorted ascending, identical on all lanes. (Validated R4/R5: rel_err = 0.)
__device__ __forceinline__ void warp_merge5(float& a0, float& a1, float& a2,
                                            float& a3, float& a4) {
#pragma unroll
    for (int off = 16; off > 0; off >>= 1) {
        float b0 = __shfl_xor_sync(0xffffffffu, a0, off);
        float b1 = __shfl_xor_sync(0xffffffffu, a1, off);
        float b2 = __shfl_xor_sync(0xffffffffu, a2, off);
        float b3 = __shfl_xor_sync(0xffffffffu, a3, off);
        float b4 = __shfl_xor_sync(0xffffffffu, a4, off);
        float c0 = fminf(a0, b4), c1 = fminf(a1, b3), c2 = fminf(a2, b2);
        float c3 = fminf(a3, b1), c4 = fminf(a4, b0);
        float l04 = fminf(c0, c4), h04 = fmaxf(c0, c4);
        float l13 = fminf(c1, c3), h13 = fmaxf(c1, c3);
        float l2h = fminf(c2, h04), h2h = fmaxf(c2, h04);
        a0 = l04;
        a1 = fminf(l13, l2h); a2 = fmaxf(l13, l2h);
        a3 = fminf(h13, h2h); a4 = fmaxf(h13, h2h);
    }
}

// ---------------------------------------------------------------------------
// Main: warp owns 4 Morton-adjacent sources, per-lane branchless top-5 over
// lane-strided candidates, expanding cubic shells over a 3D cell grid with
// exact union-5th pruning and per-row x-trimming.
// ---------------------------------------------------------------------------
__global__ __launch_bounds__(MAIN_THREADS)
void knn_main() {
    __shared__ float red_s[MAIN_WARPS];
    __shared__ int   red_c[MAIN_WARPS];

    const int lane = threadIdx.x & 31;
    const int warp = threadIdx.x >> 5;
    const int sbase = (blockIdx.x * MAIN_WARPS + warp) * SRC_PER_WARP;

    float sx[SRC_PER_WARP], sy[SRC_PER_WARP], sz[SRC_PER_WARP], s2v[SRC_PER_WARP];
    bool  sval[SRC_PER_WARP];
    float xlo = 1e30f, xhi = -1e30f, ylo = 1e30f, yhi = -1e30f;
    float zlo = 1e30f, zhi = -1e30f;
    bool any_valid = false;
#pragma unroll
    for (int s = 0; s < SRC_PER_WARP; ++s) {
        float4 v = g_ssort[sbase + s];
        sx[s] = v.x; sy[s] = v.y; sz[s] = v.z;
        sval[s] = (v.w >= 0.0f);
        s2v[s]  = fmaxf(v.w, 0.0f);
        if (sval[s]) {
            any_valid = true;
            xlo = fminf(xlo, v.x); xhi = fmaxf(xhi, v.x);
            ylo = fminf(ylo, v.y); yhi = fmaxf(yhi, v.y);
            zlo = fminf(zlo, v.z); zhi = fmaxf(zhi, v.z);
        }
    }

    float m[SRC_PER_WARP][KNN];
#pragma unroll
    for (int s = 0; s < SRC_PER_WARP; ++s)
#pragma unroll
        for (int k = 0; k < KNN; ++k) m[s][k] = 1e20f;

    if (any_valid) {
        const float XMAX = XMIN + NC * W;
        float cxlo = fminf(fmaxf(xlo, XMIN), XMAX), cxhi = fminf(fmaxf(xhi, XMIN), XMAX);
        float cylo = fminf(fmaxf(ylo, XMIN), XMAX), cyhi = fminf(fmaxf(yhi, XMIN), XMAX);
        float czlo = fminf(fmaxf(zlo, XMIN), XMAX), czhi = fminf(fmaxf(zhi, XMIN), XMAX);

        const int cx0 = cell_coord(cxlo), cx1 = cell_coord(cxhi);
        const int cy0 = cell_coord(cylo), cy1 = cell_coord(cyhi);
        const int cz0 = cell_coord(czlo), cz1 = cell_coord(czhi);

        float r2 = 1e30f;

        auto process_span = [&](int cz, int cy, int cxl, int cxr) {
            if (cxl > cxr) return;
            int base = (cz * NC + cy) * NC;
            int st = g_tstart[base + cxl];
            int en = g_tstart[base + cxr + 1];
            for (int i0 = st; i0 < en; i0 += 32) {
                int i = i0 + lane;
                float4 v = make_float4(0.0f, 0.0f, 0.0f, 1e30f);
                if (i < en) v = g_tsort[i];
#pragma unroll
                for (int s = 0; s < SRC_PER_WARP; ++s) {
                    float q = fmaf(sx[s], v.x,
                              fmaf(sy[s], v.y,
                              fmaf(sz[s], v.z, v.w)));
                    insert5(q, m[s][0], m[s][1], m[s][2], m[s][3], m[s][4]);
                }
            }
        };

        // home block: bbox cells
        for (int cz = cz0; cz <= cz1; ++cz)
            for (int cy = cy0; cy <= cy1; ++cy)
                process_span(cz, cy, cx0, cx1);

        for (int rho = 1; rho < NC; ++rho) {
            // exact union-5th pruning bound (d^2 space)
            float nr2 = 0.0f;
#pragma unroll
            for (int s = 0; s < SRC_PER_WARP; ++s) {
                float a0 = m[s][0], a1 = m[s][1], a2 = m[s][2],
                      a3 = m[s][3], a4 = m[s][4];
                warp_merge5(a0, a1, a2, a3, a4);
                if (sval[s]) nr2 = fmaxf(nr2, a4 + s2v[s]);
            }
            r2 = nr2;

            float lbr = (rho - 1) * W;
            if (lbr * lbr > r2) break;

            const int zA = cz0 - rho, zB = cz1 + rho;
            const int yA = cy0 - rho, yB = cy1 + rho;
            const int xA = cx0 - rho, xB = cx1 + rho;

            for (int cz = max(zA, 0); cz <= min(zB, NC - 1); ++cz) {
                bool zface = (cz == zA) || (cz == zB);
                float zcmin = XMIN + cz * W;
                float dz = fmaxf(fmaxf(zcmin - czhi, czlo - (zcmin + W)), 0.0f);
                float dz2 = dz * dz;
                if (dz2 > r2) continue;
                for (int cy = max(yA, 0); cy <= min(yB, NC - 1); ++cy) {
                    bool face = zface || (cy == yA) || (cy == yB);
                    float ycmin = XMIN + cy * W;
                    float dy = fmaxf(fmaxf(ycmin - cyhi, cylo - (ycmin + W)), 0.0f);
                    float dd = fmaf(dy, dy, dz2);
                    if (dd > r2) continue;
                    float dxm = sqrtf(r2 - dd);
                    int axl = cell_coord(cxlo - dxm);
                    int axr = cell_coord(cxhi + dxm);
                    if (face) {
                        int l = max(max(xA, axl), 0);
                        int rr = min(min(xB, axr), NC - 1);
                        process_span(cz, cy, l, rr);
                    } else {
                        if (xA >= 0      && xA >= axl && xA <= axr)
                            process_span(cz, cy, xA, xA);
                        if (xB <= NC - 1 && xB >= axl && xB <= axr)
                            process_span(cz, cy, xB, xB);
                    }
                }
            }
            if (zA <= 0 && zB >= NC - 1 && yA <= 0 && yB >= NC - 1 &&
                xA <= 0 && xB >= NC - 1) break;
        }
    }

    // final exact merge + loss contribution
    float wsum = 0.0f; int wcnt = 0;
#pragma unroll
    for (int s = 0; s < SRC_PER_WARP; ++s) {
        float a0 = m[s][0], a1 = m[s][1], a2 = m[s][2], a3 = m[s][3], a4 = m[s][4];
        warp_merge5(a0, a1, a2, a3, a4);
        float acc = sqrtf(fmaxf(a0 + s2v[s], 1e-12f))
                  + sqrtf(fmaxf(a1 + s2v[s], 1e-12f))
                  + sqrtf(fmaxf(a2 + s2v[s], 1e-12f))
                  + sqrtf(fmaxf(a3 + s2v[s], 1e-12f))
                  + sqrtf(fmaxf(a4 + s2v[s], 1e-12f));
        if (sval[s]) { wsum += acc; wcnt += 1; }
    }

    if (lane == 0) { red_s[warp] = wsum; red_c[warp] = wcnt; }
    __syncthreads();
    if (threadIdx.x == 0) {
        float bs = 0.0f; int bc = 0;
#pragma unroll
        for (int w = 0; w < MAIN_WARPS; ++w) { bs += red_s[w]; bc += red_c[w]; }
        g_bsum[blockIdx.x] = bs;
        g_bcnt[blockIdx.x] = bc;
    }
}

// ---------------------------------------------------------------------------
// finalize: reduce 1024 partials in double, write scalar, re-zero histograms
// for the next call (first call uses load-time zero-init).
// ---------------------------------------------------------------------------
__global__ __launch_bounds__(1024) void finalize_kernel(float* __restrict__ out) {
    __shared__ double ds[1024];
    __shared__ int    di[1024];
    int tid = threadIdx.x;
    ds[tid] = (double)g_bsum[tid];
    di[tid] = g_bcnt[tid];
    __syncthreads();
#pragma unroll
    for (int off = 512; off > 0; off >>= 1) {
        if (tid < off) { ds[tid] += ds[tid + off]; di[tid] += di[tid + off]; }
        __syncthreads();
    }
    if (tid == 0) out[0] = (float)(ds[0] / ((double)di[0] * KNN));
    for (int i = tid; i < NCELLS; i += 1024) { g_thist[i] = 0; g_shist[i] = 0; }
}

// ---------------------------------------------------------------------------
extern "C" void kernel_launch(void* const* d_in, const int* in_sizes, int n_in,
                              void* d_out, int out_size) {
    const float* src = (const float*)d_in[0];  // source_pc (2,8192,3)
    const float* tgt = (const float*)d_in[1];  // target_pc (2,8192,3)
    float* out = (float*)d_out;

    hist_kernel<<<2 * N_PTS / 256, 256>>>(src, tgt);     // launch 0
    scan_kernel<<<1, 1024>>>();                          // launch 1
    scatter_kernel<<<2 * N_PTS / 256, 256>>>(src, tgt);  // launch 2
    knn_main<<<MAIN_BLOCKS, MAIN_THREADS>>>();           // launch 3 (profiled)
    finalize_kernel<<<1, 1024>>>(out);                   // launch 4
}

// round 8
// speedup vs baseline: 1.0987x; 1.0987x over previous
#include <cuda_runtime.h>
#include <math.h>

#define N_PTS 16384            // 2*8192 points, both batches flattened
#define KNN 5
#define NC 32                  // cells per axis (3D)
#define NCELLS (NC * NC * NC)  // 32768
#define XMIN (-4.5f)
#define W (9.0f / NC)          // 0.28125
#define INV_W (NC / 9.0f)

#define MAIN_THREADS 128
#define MAIN_WARPS (MAIN_THREADS / 32)            // 4
#define SRC_PER_WARP 4
#define SRC_PER_BLOCK (MAIN_WARPS * SRC_PER_WARP) // 16
#define MAIN_BLOCKS (N_PTS / SRC_PER_BLOCK)       // 1024

// ---- scratch (zero-initialized at module load; finalize re-zeroes hists) ----
__device__ float4 g_tsort[N_PTS];   // (-2x,-2y,-2z,t^2) cell-ordered (linear z,y,x)
__device__ float4 g_ssort[N_PTS];   // (x,y,z, valid? s2 : -1) Morton-cell-ordered
__device__ int    g_thist[NCELLS];
__device__ int    g_shist[NCELLS];
__device__ int    g_tstart[NCELLS + 1];
__device__ int    g_tcur[NCELLS];
__device__ int    g_scur[NCELLS];
__device__ unsigned g_rowmask[NC];  // bit cy of word cz: row (cz,cy) nonempty
__device__ float  g_bsum[MAIN_BLOCKS];
__device__ int    g_bcnt[MAIN_BLOCKS];

__device__ __forceinline__ int cell_coord(float v) {
    int c = (int)floorf((v - XMIN) * INV_W);
    return min(NC - 1, max(0, c));
}

__device__ __forceinline__ unsigned part1by2(unsigned v) {
    v &= 0x3FF;
    v = (v | (v << 16)) & 0x030000FF;
    v = (v | (v << 8))  & 0x0300F00F;
    v = (v | (v << 4))  & 0x030C30C3;
    v = (v | (v << 2))  & 0x09249249;
    return v;
}
__device__ __forceinline__ int morton3(int cx, int cy, int cz) {
    return (int)(part1by2(cx) | (part1by2(cy) << 1) | (part1by2(cz) << 2));
}

// ---------------------------------------------------------------------------
__global__ void hist_kernel(const float* __restrict__ src,
                            const float* __restrict__ tgt) {
    int gid = blockIdx.x * blockDim.x + threadIdx.x;   // 0..32767
    if (gid < N_PTS) {
        int cx = cell_coord(tgt[3 * gid]);
        int cy = cell_coord(tgt[3 * gid + 1]);
        int cz = cell_coord(tgt[3 * gid + 2]);
        atomicAdd(&g_thist[(cz * NC + cy) * NC + cx], 1);
    } else {
        int i = gid - N_PTS;
        int cx = cell_coord(src[3 * i]);
        int cy = cell_coord(src[3 * i + 1]);
        int cz = cell_coord(src[3 * i + 2]);
        atomicAdd(&g_shist[morton3(cx, cy, cz)], 1);
    }
}

// ---------------------------------------------------------------------------
// scan: exclusive scan of both 32768-cell histograms. 1 block, 1024 threads,
// 32 cells per thread (= exactly one (z,y) row of target cells). Two global
// passes to keep register usage low. Also emits the row-occupancy bitmap.
// ---------------------------------------------------------------------------
#define CELLS_PER_T (NCELLS / 1024)   // 32
__global__ __launch_bounds__(1024) void scan_kernel() {
    __shared__ int pt[1024], ps[1024];
    const int tid = threadIdx.x;
    const int c0 = tid * CELLS_PER_T;
    int tsum = 0, ssum = 0;
    for (int j = 0; j < CELLS_PER_T; ++j) {
        tsum += g_thist[c0 + j];
        ssum += g_shist[c0 + j];
    }
    // row bitmap: thread tid covers row (cz = tid>>5, cy = tid&31)
    unsigned rowbits = __ballot_sync(0xffffffffu, tsum > 0);
    if ((tid & 31) == 0) g_rowmask[tid >> 5] = rowbits;

    pt[tid] = tsum; ps[tid] = ssum;
    __syncthreads();
    for (int off = 1; off < 1024; off <<= 1) {
        int ta = (tid >= off) ? pt[tid - off] : 0;
        int sa = (tid >= off) ? ps[tid - off] : 0;
        __syncthreads();
        pt[tid] += ta; ps[tid] += sa;
        __syncthreads();
    }
    int trun = pt[tid] - tsum;   // exclusive offsets
    int srun = ps[tid] - ssum;
    for (int j = 0; j < CELLS_PER_T; ++j) {
        int c = c0 + j;
        int tv = g_thist[c], sv = g_shist[c];
        g_tstart[c] = trun; g_tcur[c] = trun; trun += tv;
        g_scur[c] = srun;                     srun += sv;
    }
    if (tid == 1023) g_tstart[NCELLS] = N_PTS;
}

// ---------------------------------------------------------------------------
__global__ void scatter_kernel(const float* __restrict__ src,
                               const float* __restrict__ tgt) {
    int gid = blockIdx.x * blockDim.x + threadIdx.x;
    if (gid < N_PTS) {
        float x = tgt[3 * gid], y = tgt[3 * gid + 1], z = tgt[3 * gid + 2];
        bool valid = (x != 0.0f) || (y != 0.0f) || (z != 0.0f);
        float t2 = fmaf(x, x, fmaf(y, y, z * z));
        float4 v;
        if (valid) { v.x = -2.0f * x; v.y = -2.0f * y; v.z = -2.0f * z; v.w = t2; }
        else       { v.x = 0.0f;      v.y = 0.0f;      v.z = 0.0f;      v.w = 1e30f; }
        int c = (cell_coord(z) * NC + cell_coord(y)) * NC + cell_coord(x);
        g_tsort[atomicAdd(&g_tcur[c], 1)] = v;
    } else {
        int i = gid - N_PTS;
        float x = src[3 * i], y = src[3 * i + 1], z = src[3 * i + 2];
        bool valid = (x != 0.0f) || (y != 0.0f) || (z != 0.0f);
        float s2 = fmaf(x, x, fmaf(y, y, z * z));
        float4 v; v.x = x; v.y = y; v.z = z; v.w = valid ? s2 : -1.0f;
        int c = morton3(cell_coord(x), cell_coord(y), cell_coord(z));
        g_ssort[atomicAdd(&g_scur[c], 1)] = v;
    }
}

// Branchless sorted insert, ascending m0..m4 (exact no-op when q >= m4).
__device__ __forceinline__ void insert5(float q, float& m0, float& m1,
                                        float& m2, float& m3, float& m4) {
    float t0 = fminf(m0, q);
    float t1 = fminf(m1, fmaxf(m0, q));
    float t2 = fminf(m2, fmaxf(m1, q));
    float t3 = fminf(m3, fmaxf(m2, q));
    float t4 = fminf(m4, fmaxf(m3, q));
    m0 = t0; m1 = t1; m2 = t2; m3 = t3; m4 = t4;
}

// Warp butterfly merge of 32 per-lane ascending-5 lists -> exact union top-5
// sorted ascending, identical on all lanes. (Validated R4-R7: rel_err = 0.)
__device__ __forceinline__ void warp_merge5(float& a0, float& a1, float& a2,
                                            float& a3, float& a4) {
#pragma unroll
    for (int off = 16; off > 0; off >>= 1) {
        float b0 = __shfl_xor_sync(0xffffffffu, a0, off);
        float b1 = __shfl_xor_sync(0xffffffffu, a1, off);
        float b2 = __shfl_xor_sync(0xffffffffu, a2, off);
        float b3 = __shfl_xor_sync(0xffffffffu, a3, off);
        float b4 = __shfl_xor_sync(0xffffffffu, a4, off);
        float c0 = fminf(a0, b4), c1 = fminf(a1, b3), c2 = fminf(a2, b2);
        float c3 = fminf(a3, b1), c4 = fminf(a4, b0);
        float l04 = fminf(c0, c4), h04 = fmaxf(c0, c4);
        float l13 = fminf(c1, c3), h13 = fmaxf(c1, c3);
        float l2h = fminf(c2, h04), h2h = fmaxf(c2, h04);
        a0 = l04;
        a1 = fminf(l13, l2h); a2 = fmaxf(l13, l2h);
        a3 = fminf(h13, h2h); a4 = fmaxf(h13, h2h);
    }
}

// ---------------------------------------------------------------------------
// Main: warp owns 4 Morton-adjacent sources, per-lane branchless top-5,
// expanding cubic shells over a 3D cell grid. Empty (z,y) rows are skipped
// via a register-resident 1024-bit bitmap (3 instr, no LDG); empty z-slabs
// via a derived 32-bit mask.
// ---------------------------------------------------------------------------
__global__ __launch_bounds__(MAIN_THREADS)
void knn_main() {
    __shared__ float red_s[MAIN_WARPS];
    __shared__ int   red_c[MAIN_WARPS];

    const int lane = threadIdx.x & 31;
    const int warp = threadIdx.x >> 5;
    const int sbase = (blockIdx.x * MAIN_WARPS + warp) * SRC_PER_WARP;

    // lane z holds the y-bitmask of rows in z-slab `lane`
    const unsigned rw = g_rowmask[lane];
    const unsigned zmask = __ballot_sync(0xffffffffu, rw != 0u);

    float sx[SRC_PER_WARP], sy[SRC_PER_WARP], sz[SRC_PER_WARP], s2v[SRC_PER_WARP];
    bool  sval[SRC_PER_WARP];
    float xlo = 1e30f, xhi = -1e30f, ylo = 1e30f, yhi = -1e30f;
    float zlo = 1e30f, zhi = -1e30f;
    bool any_valid = false;
#pragma unroll
    for (int s = 0; s < SRC_PER_WARP; ++s) {
        float4 v = g_ssort[sbase + s];
        sx[s] = v.x; sy[s] = v.y; sz[s] = v.z;
        sval[s] = (v.w >= 0.0f);
        s2v[s]  = fmaxf(v.w, 0.0f);
        if (sval[s]) {
            any_valid = true;
            xlo = fminf(xlo, v.x); xhi = fmaxf(xhi, v.x);
            ylo = fminf(ylo, v.y); yhi = fmaxf(yhi, v.y);
            zlo = fminf(zlo, v.z); zhi = fmaxf(zhi, v.z);
        }
    }

    float m[SRC_PER_WARP][KNN];
#pragma unroll
    for (int s = 0; s < SRC_PER_WARP; ++s)
#pragma unroll
        for (int k = 0; k < KNN; ++k) m[s][k] = 1e20f;

    if (any_valid) {
        const float XMAX = XMIN + NC * W;
        float cxlo = fminf(fmaxf(xlo, XMIN), XMAX), cxhi = fminf(fmaxf(xhi, XMIN), XMAX);
        float cylo = fminf(fmaxf(ylo, XMIN), XMAX), cyhi = fminf(fmaxf(yhi, XMIN), XMAX);
        float czlo = fminf(fmaxf(zlo, XMIN), XMAX), czhi = fminf(fmaxf(zhi, XMIN), XMAX);

        const int cx0 = cell_coord(cxlo), cx1 = cell_coord(cxhi);
        const int cy0 = cell_coord(cylo), cy1 = cell_coord(cyhi);
        const int cz0 = cell_coord(czlo), cz1 = cell_coord(czhi);

        float r2 = 1e30f;

        auto row_nonempty = [&](int cz, int cy) -> bool {
            unsigned w32 = __shfl_sync(0xffffffffu, rw, cz);
            return (w32 >> cy) & 1u;
        };

        auto process_span = [&](int cz, int cy, int cxl, int cxr) {
            if (cxl > cxr) return;
            int base = (cz * NC + cy) * NC;
            int st = g_tstart[base + cxl];
            int en = g_tstart[base + cxr + 1];
            for (int i0 = st; i0 < en; i0 += 32) {
                int i = i0 + lane;
                float4 v = make_float4(0.0f, 0.0f, 0.0f, 1e30f);
                if (i < en) v = g_tsort[i];
#pragma unroll
                for (int s = 0; s < SRC_PER_WARP; ++s) {
                    float q = fmaf(sx[s], v.x,
                              fmaf(sy[s], v.y,
                              fmaf(sz[s], v.z, v.w)));
                    insert5(q, m[s][0], m[s][1], m[s][2], m[s][3], m[s][4]);
                }
            }
        };

        // home block: bbox cells
        for (int cz = cz0; cz <= cz1; ++cz)
            for (int cy = cy0; cy <= cy1; ++cy)
                if (row_nonempty(cz, cy)) process_span(cz, cy, cx0, cx1);

        for (int rho = 1; rho < NC; ++rho) {
            // exact union-5th pruning bound (d^2 space)
            float nr2 = 0.0f;
#pragma unroll
            for (int s = 0; s < SRC_PER_WARP; ++s) {
                float a0 = m[s][0], a1 = m[s][1], a2 = m[s][2],
                      a3 = m[s][3], a4 = m[s][4];
                warp_merge5(a0, a1, a2, a3, a4);
                if (sval[s]) nr2 = fmaxf(nr2, a4 + s2v[s]);
            }
            r2 = nr2;

            float lbr = (rho - 1) * W;
            if (lbr * lbr > r2) break;

            const int zA = cz0 - rho, zB = cz1 + rho;
            const int yA = cy0 - rho, yB = cy1 + rho;
            const int xA = cx0 - rho, xB = cx1 + rho;

            for (int cz = max(zA, 0); cz <= min(zB, NC - 1); ++cz) {
                if (!((zmask >> cz) & 1u)) continue;           // empty z-slab
                bool zface = (cz == zA) || (cz == zB);
                float zcmin = XMIN + cz * W;
                float dz = fmaxf(fmaxf(zcmin - czhi, czlo - (zcmin + W)), 0.0f);
                float dz2 = dz * dz;
                if (dz2 > r2) continue;
                unsigned w32 = __shfl_sync(0xffffffffu, rw, cz);
                for (int cy = max(yA, 0); cy <= min(yB, NC - 1); ++cy) {
                    if (!((w32 >> cy) & 1u)) continue;         // empty row
                    bool face = zface || (cy == yA) || (cy == yB);
                    float ycmin = XMIN + cy * W;
                    float dy = fmaxf(fmaxf(ycmin - cyhi, cylo - (ycmin + W)), 0.0f);
                    float dd = fmaf(dy, dy, dz2);
                    if (dd > r2) continue;
                    float dxm = sqrtf(r2 - dd);
                    int axl = cell_coord(cxlo - dxm);
                    int axr = cell_coord(cxhi + dxm);
                    if (face) {
                        int l = max(max(xA, axl), 0);
                        int rr = min(min(xB, axr), NC - 1);
                        process_span(cz, cy, l, rr);
                    } else {
                        if (xA >= 0      && xA >= axl && xA <= axr)
                            process_span(cz, cy, xA, xA);
                        if (xB <= NC - 1 && xB >= axl && xB <= axr)
                            process_span(cz, cy, xB, xB);
                    }
                }
            }
            if (zA <= 0 && zB >= NC - 1 && yA <= 0 && yB >= NC - 1 &&
                xA <= 0 && xB >= NC - 1) break;
        }
    }

    // final exact merge + loss contribution
    float wsum = 0.0f; int wcnt = 0;
#pragma unroll
    for (int s = 0; s < SRC_PER_WARP; ++s) {
        float a0 = m[s][0], a1 = m[s][1], a2 = m[s][2], a3 = m[s][3], a4 = m[s][4];
        warp_merge5(a0, a1, a2, a3, a4);
        float acc = sqrtf(fmaxf(a0 + s2v[s], 1e-12f))
                  + sqrtf(fmaxf(a1 + s2v[s], 1e-12f))
                  + sqrtf(fmaxf(a2 + s2v[s], 1e-12f))
                  + sqrtf(fmaxf(a3 + s2v[s], 1e-12f))
                  + sqrtf(fmaxf(a4 + s2v[s], 1e-12f));
        if (sval[s]) { wsum += acc; wcnt += 1; }
    }

    if (lane == 0) { red_s[warp] = wsum; red_c[warp] = wcnt; }
    __syncthreads();
    if (threadIdx.x == 0) {
        float bs = 0.0f; int bc = 0;
#pragma unroll
        for (int w = 0; w < MAIN_WARPS; ++w) { bs += red_s[w]; bc += red_c[w]; }
        g_bsum[blockIdx.x] = bs;
        g_bcnt[blockIdx.x] = bc;
    }
}

// ---------------------------------------------------------------------------
// finalize: reduce 1024 partials in double, write scalar, re-zero histograms
// for the next call (first call uses load-time zero-init).
// ---------------------------------------------------------------------------
__global__ __launch_bounds__(1024) void finalize_kernel(float* __restrict__ out) {
    __shared__ double ds[1024];
    __shared__ int    di[1024];
    int tid = threadIdx.x;
    ds[tid] = (double)g_bsum[tid];
    di[tid] = g_bcnt[tid];
    __syncthreads();
#pragma unroll
    for (int off = 512; off > 0; off >>= 1) {
        if (tid < off) { ds[tid] += ds[tid + off]; di[tid] += di[tid + off]; }
        __syncthreads();
    }
    if (tid == 0) out[0] = (float)(ds[0] / ((double)di[0] * KNN));
    for (int i = tid; i < NCELLS; i += 1024) { g_thist[i] = 0; g_shist[i] = 0; }
}

// ---------------------------------------------------------------------------
extern "C" void kernel_launch(void* const* d_in, const int* in_sizes, int n_in,
                              void* d_out, int out_size) {
    const float* src = (const float*)d_in[0];  // source_pc (2,8192,3)
    const float* tgt = (const float*)d_in[1];  // target_pc (2,8192,3)
    float* out = (float*)d_out;

    hist_kernel<<<2 * N_PTS / 256, 256>>>(src, tgt);     // launch 0
    scan_kernel<<<1, 1024>>>();                          // launch 1
    scatter_kernel<<<2 * N_PTS / 256, 256>>>(src, tgt);  // launch 2
    knn_main<<<MAIN_BLOCKS, MAIN_THREADS>>>();           // launch 3 (profiled)
    finalize_kernel<<<1, 1024>>>(out);                   // launch 4
}

// round 9
// speedup vs baseline: 3.0920x; 2.8142x over previous
#include <cuda_runtime.h>
#include <math.h>

#define N_PTS 16384            // 2*8192 points, both batches flattened
#define KNN 5
#define NC 32                  // cells per axis (3D)
#define NCELLS (NC * NC * NC)  // 32768
#define XMIN (-4.5f)
#define XMAXV (4.5f)
#define W (9.0f / NC)          // 0.28125
#define INV_W (NC / 9.0f)

#define MAIN_THREADS 128
#define MAIN_WARPS (MAIN_THREADS / 32)        // 4, one source per warp
#define MAIN_BLOCKS (N_PTS / MAIN_WARPS)      // 4096

// ---- scratch (zero-initialized at module load; finalize re-zeroes hists) ----
__device__ float4 g_tsort[N_PTS];   // (-2x,-2y,-2z,t^2) cell-ordered (linear z,y,x)
__device__ float4 g_ssort[N_PTS];   // (x,y,z, valid? s2 : -1) Morton-cell-ordered
__device__ int    g_thist[NCELLS];
__device__ int    g_shist[NCELLS];
__device__ int    g_tstart[NCELLS + 1];
__device__ int    g_tcur[NCELLS];
__device__ int    g_scur[NCELLS];
__device__ unsigned g_rowmask[NC];  // bit cy of word cz: row (cz,cy) nonempty
__device__ float  g_bsum[MAIN_BLOCKS];
__device__ int    g_bcnt[MAIN_BLOCKS];

__device__ __forceinline__ int cell_coord(float v) {
    int c = (int)floorf((v - XMIN) * INV_W);
    return min(NC - 1, max(0, c));
}

__device__ __forceinline__ unsigned part1by2(unsigned v) {
    v &= 0x3FF;
    v = (v | (v << 16)) & 0x030000FF;
    v = (v | (v << 8))  & 0x0300F00F;
    v = (v | (v << 4))  & 0x030C30C3;
    v = (v | (v << 2))  & 0x09249249;
    return v;
}
__device__ __forceinline__ int morton3(int cx, int cy, int cz) {
    return (int)(part1by2(cx) | (part1by2(cy) << 1) | (part1by2(cz) << 2));
}

// ---------------------------------------------------------------------------
__global__ void hist_kernel(const float* __restrict__ src,
                            const float* __restrict__ tgt) {
    int gid = blockIdx.x * blockDim.x + threadIdx.x;   // 0..32767
    if (gid < N_PTS) {
        int cx = cell_coord(tgt[3 * gid]);
        int cy = cell_coord(tgt[3 * gid + 1]);
        int cz = cell_coord(tgt[3 * gid + 2]);
        atomicAdd(&g_thist[(cz * NC + cy) * NC + cx], 1);
    } else {
        int i = gid - N_PTS;
        int cx = cell_coord(src[3 * i]);
        int cy = cell_coord(src[3 * i + 1]);
        int cz = cell_coord(src[3 * i + 2]);
        atomicAdd(&g_shist[morton3(cx, cy, cz)], 1);
    }
}

// ---------------------------------------------------------------------------
// scan: exclusive scan of both 32768-cell histograms (two global passes to
// stay register-lean). Thread tid covers exactly one (z,y) target row ->
// emits the row-occupancy bitmap for free.
// ---------------------------------------------------------------------------
#define CELLS_PER_T (NCELLS / 1024)   // 32
__global__ __launch_bounds__(1024) void scan_kernel() {
    __shared__ int pt[1024], ps[1024];
    const int tid = threadIdx.x;
    const int c0 = tid * CELLS_PER_T;
    int tsum = 0, ssum = 0;
    for (int j = 0; j < CELLS_PER_T; ++j) {
        tsum += g_thist[c0 + j];
        ssum += g_shist[c0 + j];
    }
    unsigned rowbits = __ballot_sync(0xffffffffu, tsum > 0);
    if ((tid & 31) == 0) g_rowmask[tid >> 5] = rowbits;

    pt[tid] = tsum; ps[tid] = ssum;
    __syncthreads();
    for (int off = 1; off < 1024; off <<= 1) {
        int ta = (tid >= off) ? pt[tid - off] : 0;
        int sa = (tid >= off) ? ps[tid - off] : 0;
        __syncthreads();
        pt[tid] += ta; ps[tid] += sa;
        __syncthreads();
    }
    int trun = pt[tid] - tsum;
    int srun = ps[tid] - ssum;
    for (int j = 0; j < CELLS_PER_T; ++j) {
        int c = c0 + j;
        int tv = g_thist[c], sv = g_shist[c];
        g_tstart[c] = trun; g_tcur[c] = trun; trun += tv;
        g_scur[c] = srun;                     srun += sv;
    }
    if (tid == 1023) g_tstart[NCELLS] = N_PTS;
}

// ---------------------------------------------------------------------------
__global__ void scatter_kernel(const float* __restrict__ src,
                               const float* __restrict__ tgt) {
    int gid = blockIdx.x * blockDim.x + threadIdx.x;
    if (gid < N_PTS) {
        float x = tgt[3 * gid], y = tgt[3 * gid + 1], z = tgt[3 * gid + 2];
        bool valid = (x != 0.0f) || (y != 0.0f) || (z != 0.0f);
        float t2 = fmaf(x, x, fmaf(y, y, z * z));
        float4 v;
        if (valid) { v.x = -2.0f * x; v.y = -2.0f * y; v.z = -2.0f * z; v.w = t2; }
        else       { v.x = 0.0f;      v.y = 0.0f;      v.z = 0.0f;      v.w = 1e30f; }
        int c = (cell_coord(z) * NC + cell_coord(y)) * NC + cell_coord(x);
        g_tsort[atomicAdd(&g_tcur[c], 1)] = v;
    } else {
        int i = gid - N_PTS;
        float x = src[3 * i], y = src[3 * i + 1], z = src[3 * i + 2];
        bool valid = (x != 0.0f) || (y != 0.0f) || (z != 0.0f);
        float s2 = fmaf(x, x, fmaf(y, y, z * z));
        float4 v; v.x = x; v.y = y; v.z = z; v.w = valid ? s2 : -1.0f;
        int c = morton3(cell_coord(x), cell_coord(y), cell_coord(z));
        g_ssort[atomicAdd(&g_scur[c], 1)] = v;
    }
}

// Branchless sorted insert, ascending m0..m4 (exact no-op when q >= m4).
__device__ __forceinline__ void insert5(float q, float& m0, float& m1,
                                        float& m2, float& m3, float& m4) {
    float t0 = fminf(m0, q);
    float t1 = fminf(m1, fmaxf(m0, q));
    float t2 = fminf(m2, fmaxf(m1, q));
    float t3 = fminf(m3, fmaxf(m2, q));
    float t4 = fminf(m4, fmaxf(m3, q));
    m0 = t0; m1 = t1; m2 = t2; m3 = t3; m4 = t4;
}

// Warp butterfly merge of 32 per-lane ascending-5 lists -> exact union top-5
// sorted ascending, identical on all lanes. (Validated R4-R8: rel_err = 0.)
__device__ __forceinline__ void warp_merge5(float& a0, float& a1, float& a2,
                                            float& a3, float& a4) {
#pragma unroll
    for (int off = 16; off > 0; off >>= 1) {
        float b0 = __shfl_xor_sync(0xffffffffu, a0, off);
        float b1 = __shfl_xor_sync(0xffffffffu, a1, off);
        float b2 = __shfl_xor_sync(0xffffffffu, a2, off);
        float b3 = __shfl_xor_sync(0xffffffffu, a3, off);
        float b4 = __shfl_xor_sync(0xffffffffu, a4, off);
        float c0 = fminf(a0, b4), c1 = fminf(a1, b3), c2 = fminf(a2, b2);
        float c3 = fminf(a3, b1), c4 = fminf(a4, b0);
        float l04 = fminf(c0, c4), h04 = fmaxf(c0, c4);
        float l13 = fminf(c1, c3), h13 = fmaxf(c1, c3);
        float l2h = fminf(c2, h04), h2h = fmaxf(c2, h04);
        a0 = l04;
        a1 = fminf(l13, l2h); a2 = fmaxf(l13, l2h);
        a3 = fminf(h13, h2h); a4 = fmaxf(h13, h2h);
    }
}

// ---------------------------------------------------------------------------
// Main: ONE source per warp. Per-lane branchless top-5 over lane-strided
// candidates; expanding cubic shells around the source's own cell with tight
// point-to-cell bounds, exact union-5th pruning, bitmap row skipping, and
// per-row x-trimming. No inter-source coupling, no bbox.
// ---------------------------------------------------------------------------
__global__ __launch_bounds__(MAIN_THREADS)
void knn_main() {
    __shared__ float red_s[MAIN_WARPS];
    __shared__ int   red_c[MAIN_WARPS];

    const int lane = threadIdx.x & 31;
    const int warp = threadIdx.x >> 5;
    const int sid  = blockIdx.x * MAIN_WARPS + warp;

    const unsigned rw = g_rowmask[lane];                 // lane z's y-bitmask
    const unsigned zmask = __ballot_sync(0xffffffffu, rw != 0u);

    float4 sv = g_ssort[sid];                            // uniform across warp
    const float sx = sv.x, sy = sv.y, sz = sv.z;
    const bool  valid = (sv.w >= 0.0f);
    const float s2 = fmaxf(sv.w, 0.0f);

    float m0 = 1e20f, m1 = 1e20f, m2 = 1e20f, m3 = 1e20f, m4 = 1e20f;

    if (valid) {
        const float px = fminf(fmaxf(sx, XMIN), XMAXV);
        const float py = fminf(fmaxf(sy, XMIN), XMAXV);
        const float pz = fminf(fmaxf(sz, XMIN), XMAXV);
        const int ccx = cell_coord(px);
        const int ccy = cell_coord(py);
        const int ccz = cell_coord(pz);

        auto process_span = [&](int cz, int cy, int cxl, int cxr) {
            int base = (cz * NC + cy) * NC;
            int st = g_tstart[base + cxl];
            int en = g_tstart[base + cxr + 1];
            for (int i0 = st; i0 < en; i0 += 32) {
                int i = i0 + lane;
                float4 v = make_float4(0.0f, 0.0f, 0.0f, 1e30f);
                if (i < en) v = g_tsort[i];
                float q = fmaf(sx, v.x, fmaf(sy, v.y, fmaf(sz, v.z, v.w)));
                insert5(q, m0, m1, m2, m3, m4);
            }
        };

        // home cell
        if ((__shfl_sync(0xffffffffu, rw, ccz) >> ccy) & 1u)
            process_span(ccz, ccy, ccx, ccx);

        for (int rho = 1; rho < NC; ++rho) {
            float a0 = m0, a1 = m1, a2 = m2, a3 = m3, a4 = m4;
            warp_merge5(a0, a1, a2, a3, a4);
            float r2 = a4 + s2;                 // current d5^2 upper bound

            float lbr = (rho - 1) * W;
            if (lbr * lbr > r2) break;

            const int zA = ccz - rho, zB = ccz + rho;
            const int yA = ccy - rho, yB = ccy + rho;
            const int xA = ccx - rho, xB = ccx + rho;

            for (int cz = max(zA, 0); cz <= min(zB, NC - 1); ++cz) {
                if (!((zmask >> cz) & 1u)) continue;
                float zcmin = XMIN + cz * W;
                float dz = fmaxf(fmaxf(zcmin - pz, pz - (zcmin + W)), 0.0f);
                float dz2 = dz * dz;
                if (dz2 > r2) continue;
                bool zface = (cz == zA) || (cz == zB);
                unsigned w32 = __shfl_sync(0xffffffffu, rw, cz);
                for (int cy = max(yA, 0); cy <= min(yB, NC - 1); ++cy) {
                    if (!((w32 >> cy) & 1u)) continue;
                    bool face = zface || (cy == yA) || (cy == yB);
                    float ycmin = XMIN + cy * W;
                    float dy = fmaxf(fmaxf(ycmin - py, py - (ycmin + W)), 0.0f);
                    float dd = fmaf(dy, dy, dz2);
                    if (dd > r2) continue;
                    float dxm = sqrtf(r2 - dd);
                    int axl = cell_coord(px - dxm);
                    int axr = cell_coord(px + dxm);
                    if (face) {
                        int l  = max(max(xA, axl), 0);
                        int rr = min(min(xB, axr), NC - 1);
                        if (l <= rr) process_span(cz, cy, l, rr);
                    } else {
                        if (xA >= 0 && xA >= axl && xA <= axr)
                            process_span(cz, cy, xA, xA);
                        if (xB <= NC - 1 && xB >= axl && xB <= axr)
                            process_span(cz, cy, xB, xB);
                    }
                }
            }
            if (zA <= 0 && zB >= NC - 1 && yA <= 0 && yB >= NC - 1 &&
                xA <= 0 && xB >= NC - 1) break;
        }
    }

    // final exact merge + loss contribution (lists identical on all lanes after)
    warp_merge5(m0, m1, m2, m3, m4);
    float wsum = 0.0f; int wcnt = 0;
    if (valid) {
        wsum = sqrtf(fmaxf(m0 + s2, 1e-12f))
             + sqrtf(fmaxf(m1 + s2, 1e-12f))
             + sqrtf(fmaxf(m2 + s2, 1e-12f))
             + sqrtf(fmaxf(m3 + s2, 1e-12f))
             + sqrtf(fmaxf(m4 + s2, 1e-12f));
        wcnt = 1;
    }

    if (lane == 0) { red_s[warp] = wsum; red_c[warp] = wcnt; }
    __syncthreads();
    if (threadIdx.x == 0) {
        float bs = 0.0f; int bc = 0;
#pragma unroll
        for (int w = 0; w < MAIN_WARPS; ++w) { bs += red_s[w]; bc += red_c[w]; }
        g_bsum[blockIdx.x] = bs;
        g_bcnt[blockIdx.x] = bc;
    }
}

// ---------------------------------------------------------------------------
// finalize: reduce 4096 partials in double, write scalar, re-zero histograms
// for the next call (first call uses load-time zero-init).
// ---------------------------------------------------------------------------
__global__ __launch_bounds__(1024) void finalize_kernel(float* __restrict__ out) {
    __shared__ double ds[1024];
    __shared__ int    di[1024];
    int tid = threadIdx.x;
    double s = 0.0; int c = 0;
#pragma unroll
    for (int j = 0; j < MAIN_BLOCKS / 1024; ++j) {
        int i = j * 1024 + tid;
        s += (double)g_bsum[i];
        c += g_bcnt[i];
    }
    ds[tid] = s; di[tid] = c;
    __syncthreads();
#pragma unroll
    for (int off = 512; off > 0; off >>= 1) {
        if (tid < off) { ds[tid] += ds[tid + off]; di[tid] += di[tid + off]; }
        __syncthreads();
    }
    if (tid == 0) out[0] = (float)(ds[0] / ((double)di[0] * KNN));
    for (int i = tid; i < NCELLS; i += 1024) { g_thist[i] = 0; g_shist[i] = 0; }
}

// ---------------------------------------------------------------------------
extern "C" void kernel_launch(void* const* d_in, const int* in_sizes, int n_in,
                              void* d_out, int out_size) {
    const float* src = (const float*)d_in[0];  // source_pc (2,8192,3)
    const float* tgt = (const float*)d_in[1];  // target_pc (2,8192,3)
    float* out = (float*)d_out;

    hist_kernel<<<2 * N_PTS / 256, 256>>>(src, tgt);     // launch 0
    scan_kernel<<<1, 1024>>>();                          // launch 1
    scatter_kernel<<<2 * N_PTS / 256, 256>>>(src, tgt);  // launch 2
    knn_main<<<MAIN_BLOCKS, MAIN_THREADS>>>();           // launch 3 (profiled)
    finalize_kernel<<<1, 1024>>>(out);                   // launch 4
}

// round 10
// speedup vs baseline: 8.4155x; 2.7217x over previous
#include <cuda_runtime.h>
#include <math.h>

#define N_PTS 16384            // 2*8192 points, both batches flattened
#define KNN 5
#define NC 32                  // cells per axis (3D)
#define NCELLS (NC * NC * NC)  // 32768
#define XMIN (-4.5f)
#define XMAXV (4.5f)
#define W (9.0f / NC)          // 0.28125
#define INV_W (NC / 9.0f)

#define MAIN_THREADS 128
#define MAIN_WARPS 4                       // one source per warp
#define MAIN_BLOCKS (N_PTS / MAIN_WARPS)   // 4096

// ---- scratch (zero-initialized at module load; scan3 re-zeroes hists) ----
__device__ float4 g_tsort[N_PTS];   // (-2x,-2y,-2z,t^2) cell-ordered (linear z,y,x)
__device__ float4 g_ssort[N_PTS];   // (x,y,z, valid? s2 : -1) Morton-cell-ordered
__device__ int    g_thist[NCELLS];
__device__ int    g_shist[NCELLS];
__device__ int    g_tstart[NCELLS + 1];
__device__ int    g_tcur[NCELLS];
__device__ int    g_scur[NCELLS];
__device__ int    g_ttot[32], g_stot[32];
__device__ unsigned g_rowmask[NC];  // bit cy of word cz: target row (cz,cy) nonempty
__device__ float  g_bsum[MAIN_BLOCKS];
__device__ int    g_bcnt[MAIN_BLOCKS];

__device__ __forceinline__ int cell_coord(float v) {
    int c = (int)floorf((v - XMIN) * INV_W);
    return min(NC - 1, max(0, c));
}

__device__ __forceinline__ unsigned part1by2(unsigned v) {
    v &= 0x3FF;
    v = (v | (v << 16)) & 0x030000FF;
    v = (v | (v << 8))  & 0x0300F00F;
    v = (v | (v << 4))  & 0x030C30C3;
    v = (v | (v << 2))  & 0x09249249;
    return v;
}
__device__ __forceinline__ int morton3(int cx, int cy, int cz) {
    return (int)(part1by2(cx) | (part1by2(cy) << 1) | (part1by2(cz) << 2));
}

// ---------------------------------------------------------------------------
__global__ void hist_kernel(const float* __restrict__ src,
                            const float* __restrict__ tgt) {
    int gid = blockIdx.x * blockDim.x + threadIdx.x;   // 0..32767
    if (gid < N_PTS) {
        int cx = cell_coord(tgt[3 * gid]);
        int cy = cell_coord(tgt[3 * gid + 1]);
        int cz = cell_coord(tgt[3 * gid + 2]);
        atomicAdd(&g_thist[(cz * NC + cy) * NC + cx], 1);
    } else {
        int i = gid - N_PTS;
        int cx = cell_coord(src[3 * i]);
        int cy = cell_coord(src[3 * i + 1]);
        int cz = cell_coord(src[3 * i + 2]);
        atomicAdd(&g_shist[morton3(cx, cy, cz)], 1);
    }
}

// ---------------------------------------------------------------------------
// scan1: 32 blocks x 1024 threads, ONE cell per thread (fully coalesced).
// Block-local exclusive scan (smem Hillis-Steele) + block totals + rowmask.
// (The R7-R9 scan owned 32 consecutive cells per thread -> 32-way uncoalesced
//  loads through a single SM = ~150us. This replacement is ~3us.)
// ---------------------------------------------------------------------------
__global__ __launch_bounds__(1024) void scan1_kernel() {
    __shared__ int pt[1024], ps[1024];
    __shared__ unsigned rowocc;
    const int tid = threadIdx.x, b = blockIdx.x;
    const int c = b * 1024 + tid;
    int tv = g_thist[c], sv = g_shist[c];
    if (tid == 0) rowocc = 0u;
    unsigned xbits = __ballot_sync(0xffffffffu, tv > 0);   // warp = one (z,y) row
    __syncthreads();
    if ((tid & 31) == 0 && xbits) atomicOr(&rowocc, 1u << (tid >> 5));
    pt[tid] = tv; ps[tid] = sv;
    __syncthreads();
    for (int off = 1; off < 1024; off <<= 1) {
        int ta = (tid >= off) ? pt[tid - off] : 0;
        int sa = (tid >= off) ? ps[tid - off] : 0;
        __syncthreads();
        pt[tid] += ta; ps[tid] += sa;
        __syncthreads();
    }
    g_tstart[c] = pt[tid] - tv;   // exclusive within block
    g_scur[c]   = ps[tid] - sv;
    if (tid == 1023) {
        g_ttot[b] = pt[tid];
        g_stot[b] = ps[tid];
        g_rowmask[b] = rowocc;     // block b == z-slab b (1024 cells = 32 rows)
    }
}

// scan2: exclusive scan of the 32 block totals (single warp).
__global__ void scan2_kernel() {
    int tid = threadIdx.x;   // blockDim = 32
    int t = g_ttot[tid], s = g_stot[tid];
    int ti = t, si = s;
#pragma unroll
    for (int off = 1; off < 32; off <<= 1) {
        int a = __shfl_up_sync(0xffffffffu, ti, off);
        int b = __shfl_up_sync(0xffffffffu, si, off);
        if (tid >= off) { ti += a; si += b; }
    }
    g_ttot[tid] = ti - t;
    g_stot[tid] = si - s;
}

// scan3: add block offsets; init cursors; zero hists for the next call.
__global__ __launch_bounds__(1024) void scan3_kernel() {
    const int tid = threadIdx.x, b = blockIdx.x;
    const int c = b * 1024 + tid;
    int t = g_tstart[c] + g_ttot[b];
    g_tstart[c] = t;  g_tcur[c] = t;
    g_scur[c] += g_stot[b];
    g_thist[c] = 0;   g_shist[c] = 0;
    if (c == 0) g_tstart[NCELLS] = N_PTS;
}

// ---------------------------------------------------------------------------
__global__ void scatter_kernel(const float* __restrict__ src,
                               const float* __restrict__ tgt) {
    int gid = blockIdx.x * blockDim.x + threadIdx.x;
    if (gid < N_PTS) {
        float x = tgt[3 * gid], y = tgt[3 * gid + 1], z = tgt[3 * gid + 2];
        bool valid = (x != 0.0f) || (y != 0.0f) || (z != 0.0f);
        float t2 = fmaf(x, x, fmaf(y, y, z * z));
        float4 v;
        if (valid) { v.x = -2.0f * x; v.y = -2.0f * y; v.z = -2.0f * z; v.w = t2; }
        else       { v.x = 0.0f;      v.y = 0.0f;      v.z = 0.0f;      v.w = 1e30f; }
        int c = (cell_coord(z) * NC + cell_coord(y)) * NC + cell_coord(x);
        g_tsort[atomicAdd(&g_tcur[c], 1)] = v;
    } else {
        int i = gid - N_PTS;
        float x = src[3 * i], y = src[3 * i + 1], z = src[3 * i + 2];
        bool valid = (x != 0.0f) || (y != 0.0f) || (z != 0.0f);
        float s2 = fmaf(x, x, fmaf(y, y, z * z));
        float4 v; v.x = x; v.y = y; v.z = z; v.w = valid ? s2 : -1.0f;
        int c = morton3(cell_coord(x), cell_coord(y), cell_coord(z));
        g_ssort[atomicAdd(&g_scur[c], 1)] = v;
    }
}

// Branchless sorted insert, ascending m0..m4 (exact no-op when q >= m4).
__device__ __forceinline__ void insert5(float q, float& m0, float& m1,
                                        float& m2, float& m3, float& m4) {
    float t0 = fminf(m0, q);
    float t1 = fminf(m1, fmaxf(m0, q));
    float t2 = fminf(m2, fmaxf(m1, q));
    float t3 = fminf(m3, fmaxf(m2, q));
    float t4 = fminf(m4, fmaxf(m3, q));
    m0 = t0; m1 = t1; m2 = t2; m3 = t3; m4 = t4;
}

// Warp butterfly merge of 32 per-lane ascending-5 lists -> exact union top-5
// sorted ascending, identical on all lanes. (Validated R4-R9: rel_err = 0.)
__device__ __forceinline__ void warp_merge5(float& a0, float& a1, float& a2,
                                            float& a3, float& a4) {
#pragma unroll
    for (int off = 16; off > 0; off >>= 1) {
        float b0 = __shfl_xor_sync(0xffffffffu, a0, off);
        float b1 = __shfl_xor_sync(0xffffffffu, a1, off);
        float b2 = __shfl_xor_sync(0xffffffffu, a2, off);
        float b3 = __shfl_xor_sync(0xffffffffu, a3, off);
        float b4 = __shfl_xor_sync(0xffffffffu, a4, off);
        float c0 = fminf(a0, b4), c1 = fminf(a1, b3), c2 = fminf(a2, b2);
        float c3 = fminf(a3, b1), c4 = fminf(a4, b0);
        float l04 = fminf(c0, c4), h04 = fmaxf(c0, c4);
        float l13 = fminf(c1, c3), h13 = fmaxf(c1, c3);
        float l2h = fminf(c2, h04), h2h = fmaxf(c2, h04);
        a0 = l04;
        a1 = fminf(l13, l2h); a2 = fmaxf(l13, l2h);
        a3 = fminf(h13, h2h); a4 = fmaxf(h13, h2h);
    }
}

// ---------------------------------------------------------------------------
// Main: one source per warp (strided across blocks for balance).
// Phase 1 (seed): home cell, expanding full shells only until >=5 candidates.
// One exact union merge -> tight r2.
// Phase 2 (sphere): single pass over rows within sqrt(r2), bitmap row skip,
// per-row x-trim, seed-cube exclusion (no duplicates), cheap r2 refresh.
// ---------------------------------------------------------------------------
__global__ __launch_bounds__(MAIN_THREADS)
void knn_main() {
    __shared__ float red_s[MAIN_WARPS];
    __shared__ int   red_c[MAIN_WARPS];

    const int lane = threadIdx.x & 31;
    const int warp = threadIdx.x >> 5;
    const int sid  = blockIdx.x + warp * MAIN_BLOCKS;    // stride-mix for balance

    const unsigned rw = g_rowmask[lane];                 // lane z's y-bitmask
    const unsigned zmask = __ballot_sync(0xffffffffu, rw != 0u);

    float4 sv = g_ssort[sid];
    const float sx = sv.x, sy = sv.y, sz = sv.z;
    const bool  valid = (sv.w >= 0.0f);
    const float s2 = fmaxf(sv.w, 0.0f);

    float m0 = 1e20f, m1 = 1e20f, m2 = 1e20f, m3 = 1e20f, m4 = 1e20f;

    if (valid) {
        const float px = fminf(fmaxf(sx, XMIN), XMAXV);
        const float py = fminf(fmaxf(sy, XMIN), XMAXV);
        const float pz = fminf(fmaxf(sz, XMIN), XMAXV);
        const int ccx = cell_coord(px);
        const int ccy = cell_coord(py);
        const int ccz = cell_coord(pz);

        int seen = 0;

        auto rowbits = [&](int cz) -> unsigned {
            return __shfl_sync(0xffffffffu, rw, cz);
        };
        auto span = [&](int cz, int cy, int cxl, int cxr) {
            int base = (cz * NC + cy) * NC;
            int st = g_tstart[base + cxl];
            int en = g_tstart[base + cxr + 1];
            seen += en - st;
            for (int i0 = st; i0 < en; i0 += 32) {
                int i = i0 + lane;
                float4 v = make_float4(0.0f, 0.0f, 0.0f, 1e30f);
                if (i < en) v = g_tsort[i];
                float q = fmaf(sx, v.x, fmaf(sy, v.y, fmaf(sz, v.z, v.w)));
                insert5(q, m0, m1, m2, m3, m4);
            }
        };

        // ---- seed: home cell, then full shells until >=5 candidates seen ----
        if ((rowbits(ccz) >> ccy) & 1u) span(ccz, ccy, ccx, ccx);
        int rs = 0;
        while (seen < KNN && rs < NC) {
            ++rs;
            const int zA = ccz - rs, zB = ccz + rs;
            const int yA = ccy - rs, yB = ccy + rs;
            const int xA = ccx - rs, xB = ccx + rs;
            const int xl = max(xA, 0), xr = min(xB, NC - 1);
            for (int cz = max(zA, 0); cz <= min(zB, NC - 1); ++cz) {
                if (!((zmask >> cz) & 1u)) continue;
                unsigned w32 = rowbits(cz);
                if (!w32) continue;
                if (cz == zA || cz == zB) {           // full z-face
                    for (int cy = max(yA, 0); cy <= min(yB, NC - 1); ++cy)
                        if ((w32 >> cy) & 1u) span(cz, cy, xl, xr);
                } else {
                    if (yA >= 0      && ((w32 >> yA) & 1u)) span(cz, yA, xl, xr);
                    if (yB <= NC - 1 && ((w32 >> yB) & 1u)) span(cz, yB, xl, xr);
                    for (int cy = max(yA + 1, 0); cy <= min(yB - 1, NC - 1); ++cy) {
                        if (!((w32 >> cy) & 1u)) continue;
                        if (xA >= 0)      span(cz, cy, xA, xA);
                        if (xB <= NC - 1) span(cz, cy, xB, xB);
                    }
                }
            }
        }

        // exact union-5th bound from seed (computed on copies; lane lists intact)
        float r2;
        {
            float a0 = m0, a1 = m1, a2 = m2, a3 = m3, a4 = m4;
            warp_merge5(a0, a1, a2, a3, a4);
            r2 = a4 + s2;
        }

        // ---- sphere pass: all rows within sqrt(r2), minus the seed cube ----
        const int szA = ccz - rs, szB = ccz + rs;
        const int syA = ccy - rs, syB = ccy + rs;
        const int sxA = ccx - rs, sxB = ccx + rs;

        float rmax = sqrtf(r2);
        const int czmin = cell_coord(pz - rmax);
        const int czmax = cell_coord(pz + rmax);

        for (int cz = czmin; cz <= czmax; ++cz) {
            if (!((zmask >> cz) & 1u)) continue;
            float zcmin = XMIN + cz * W;
            float dz = fmaxf(fmaxf(zcmin - pz, pz - (zcmin + W)), 0.0f);
            float dz2 = dz * dz;
            if (dz2 > r2) continue;
            unsigned w32 = rowbits(cz);
            if (!w32) continue;
            float ry = sqrtf(fmaxf(r2 - dz2, 0.0f));
            const int cya = cell_coord(py - ry);
            const int cyb = cell_coord(py + ry);
            const bool zin = (cz >= szA) && (cz <= szB);
            for (int cy = cya; cy <= cyb; ++cy) {
                if (!((w32 >> cy) & 1u)) continue;
                float ycmin = XMIN + cy * W;
                float dy = fmaxf(fmaxf(ycmin - py, py - (ycmin + W)), 0.0f);
                float dd = fmaf(dy, dy, dz2);
                if (dd > r2) continue;
                float dxm = sqrtf(r2 - dd);
                int axl = cell_coord(px - dxm);
                int axr = cell_coord(px + dxm);
                if (zin && cy >= syA && cy <= syB) {
                    // exclude already-seeded x range [sxA, sxB]
                    int r1 = min(axr, sxA - 1);
                    if (axl <= r1) span(cz, cy, axl, r1);
                    int l2 = max(axl, sxB + 1);
                    if (l2 <= axr) span(cz, cy, l2, axr);
                } else {
                    span(cz, cy, axl, axr);
                }
                // cheap valid refresh: min over lanes of m4 >= union-5th
                float mm = m4;
#pragma unroll
                for (int off = 16; off > 0; off >>= 1)
                    mm = fminf(mm, __shfl_xor_sync(0xffffffffu, mm, off));
                r2 = fminf(r2, mm + s2);
            }
        }
    }

    // final exact merge + loss contribution (lists identical on lanes after)
    warp_merge5(m0, m1, m2, m3, m4);
    float wsum = 0.0f; int wcnt = 0;
    if (valid) {
        wsum = sqrtf(fmaxf(m0 + s2, 1e-12f))
             + sqrtf(fmaxf(m1 + s2, 1e-12f))
             + sqrtf(fmaxf(m2 + s2, 1e-12f))
             + sqrtf(fmaxf(m3 + s2, 1e-12f))
             + sqrtf(fmaxf(m4 + s2, 1e-12f));
        wcnt = 1;
    }

    if (lane == 0) { red_s[warp] = wsum; red_c[warp] = wcnt; }
    __syncthreads();
    if (threadIdx.x == 0) {
        float bs = 0.0f; int bc = 0;
#pragma unroll
        for (int w = 0; w < MAIN_WARPS; ++w) { bs += red_s[w]; bc += red_c[w]; }
        g_bsum[blockIdx.x] = bs;
        g_bcnt[blockIdx.x] = bc;
    }
}

// ---------------------------------------------------------------------------
__global__ __launch_bounds__(1024) void finalize_kernel(float* __restrict__ out) {
    __shared__ double ds[1024];
    __shared__ int    di[1024];
    int tid = threadIdx.x;
    double s = 0.0; int c = 0;
#pragma unroll
    for (int j = 0; j < MAIN_BLOCKS / 1024; ++j) {
        int i = j * 1024 + tid;
        s += (double)g_bsum[i];
        c += g_bcnt[i];
    }
    ds[tid] = s; di[tid] = c;
    __syncthreads();
#pragma unroll
    for (int off = 512; off > 0; off >>= 1) {
        if (tid < off) { ds[tid] += ds[tid + off]; di[tid] += di[tid + off]; }
        __syncthreads();
    }
    if (tid == 0) out[0] = (float)(ds[0] / ((double)di[0] * KNN));
}

// ---------------------------------------------------------------------------
extern "C" void kernel_launch(void* const* d_in, const int* in_sizes, int n_in,
                              void* d_out, int out_size) {
    const float* src = (const float*)d_in[0];  // source_pc (2,8192,3)
    const float* tgt = (const float*)d_in[1];  // target_pc (2,8192,3)
    float* out = (float*)d_out;

    hist_kernel<<<2 * N_PTS / 256, 256>>>(src, tgt);     // launch 0
    scan1_kernel<<<32, 1024>>>();                        // launch 1
    scan2_kernel<<<1, 32>>>();                           // launch 2
    scan3_kernel<<<32, 1024>>>();                        // launch 3
    scatter_kernel<<<2 * N_PTS / 256, 256>>>(src, tgt);  // launch 4
    knn_main<<<MAIN_BLOCKS, MAIN_THREADS>>>();           // launch 5 (profiled)
    finalize_kernel<<<1, 1024>>>(out);                   // launch 6
}

// round 11
// speedup vs baseline: 10.2086x; 1.2131x over previous
#include <cuda_runtime.h>
#include <math.h>

#define N_PTS 16384            // 2*8192 points, both batches flattened
#define KNN 5
#define NC 32                  // cells per axis (3D)
#define NCELLS (NC * NC * NC)  // 32768
#define XMIN (-4.5f)
#define XMAXV (4.5f)
#define W (9.0f / NC)          // 0.28125
#define INV_W (NC / 9.0f)

#define MAIN_THREADS 128
#define MAIN_WARPS 4                       // one source per warp
#define MAIN_BLOCKS (N_PTS / MAIN_WARPS)   // 4096

// ---- scratch (zero-initialized at module load; re-zeroed in-pipeline) ----
__device__ float4 g_tsort[N_PTS];   // (-2x,-2y,-2z,t^2) cell-ordered (linear z,y,x)
__device__ float4 g_ssort[N_PTS];   // (x,y,z, valid? s2 : -1) Morton-cell-ordered
__device__ int    g_thist[NCELLS];
__device__ int    g_shist[NCELLS];
__device__ int    g_tstart[NCELLS + 1];
__device__ int    g_tcur[NCELLS];
__device__ int    g_scur[NCELLS];
__device__ int    g_pubT[32], g_pubS[32];
__device__ int    g_flag[32];       // lookback flags (zeroed by finalize)
__device__ unsigned g_rowmask[NC];  // bit cy of word cz: target row (cz,cy) nonempty
__device__ float  g_bsum[MAIN_BLOCKS];
__device__ int    g_bcnt[MAIN_BLOCKS];

__device__ __forceinline__ int cell_coord(float v) {
    int c = (int)floorf((v - XMIN) * INV_W);
    return min(NC - 1, max(0, c));
}

__device__ __forceinline__ unsigned part1by2(unsigned v) {
    v &= 0x3FF;
    v = (v | (v << 16)) & 0x030000FF;
    v = (v | (v << 8))  & 0x0300F00F;
    v = (v | (v << 4))  & 0x030C30C3;
    v = (v | (v << 2))  & 0x09249249;
    return v;
}
__device__ __forceinline__ int morton3(int cx, int cy, int cz) {
    return (int)(part1by2(cx) | (part1by2(cy) << 1) | (part1by2(cz) << 2));
}

// ---------------------------------------------------------------------------
__global__ void hist_kernel(const float* __restrict__ src,
                            const float* __restrict__ tgt) {
    int gid = blockIdx.x * blockDim.x + threadIdx.x;   // 0..32767
    if (gid < N_PTS) {
        int cx = cell_coord(tgt[3 * gid]);
        int cy = cell_coord(tgt[3 * gid + 1]);
        int cz = cell_coord(tgt[3 * gid + 2]);
        atomicAdd(&g_thist[(cz * NC + cy) * NC + cx], 1);
    } else {
        int i = gid - N_PTS;
        int cx = cell_coord(src[3 * i]);
        int cy = cell_coord(src[3 * i + 1]);
        int cz = cell_coord(src[3 * i + 2]);
        atomicAdd(&g_shist[morton3(cx, cy, cz)], 1);
    }
}

// ---------------------------------------------------------------------------
// scan: ONE kernel, 32 co-resident blocks x 1024 threads, one cell/thread
// (coalesced). Block-local smem scan; cross-block offsets via publish +
// lookback spin (all 32 blocks resident on 148 SMs -> deadlock-free).
// Emits tstart/tcur/scur + rowmask, and re-zeroes the histograms.
// ---------------------------------------------------------------------------
__global__ __launch_bounds__(1024) void scan_kernel() {
    __shared__ int pt[1024], ps[1024];
    __shared__ int vT[32], vS[32];
    __shared__ unsigned rowocc;
    const int tid = threadIdx.x, b = blockIdx.x;
    const int c = b * 1024 + tid;
    int tv = g_thist[c], sv = g_shist[c];
    if (tid == 0) rowocc = 0u;
    // rowmask: each warp covers exactly one (z,y) row of 32 x-cells
    unsigned xbits = __ballot_sync(0xffffffffu, tv > 0);
    __syncthreads();
    if ((tid & 31) == 0 && xbits) atomicOr(&rowocc, 1u << (tid >> 5));
    pt[tid] = tv; ps[tid] = sv;
    __syncthreads();
    for (int off = 1; off < 1024; off <<= 1) {
        int ta = (tid >= off) ? pt[tid - off] : 0;
        int sa = (tid >= off) ? ps[tid - off] : 0;
        __syncthreads();
        pt[tid] += ta; ps[tid] += sa;
        __syncthreads();
    }
    if (tid == 1023) {
        g_pubT[b] = pt[1023];
        g_pubS[b] = ps[1023];
        __threadfence();
        *((volatile int*)&g_flag[b]) = 1;
        g_rowmask[b] = rowocc;          // block b == z-slab b
    }
    // first warp gathers predecessor totals (spin until published)
    if (tid < 32) {
        int t = 0, s = 0;
        if (tid < b) {
            while (*((volatile int*)&g_flag[tid]) == 0) {}
            t = *((volatile int*)&g_pubT[tid]);
            s = *((volatile int*)&g_pubS[tid]);
        }
        vT[tid] = t; vS[tid] = s;
    }
    __syncthreads();
    int bofT = 0, bofS = 0;
    if (tid == 0) {
        for (int i = 0; i < 32; ++i) { bofT += vT[i]; bofS += vS[i]; }
        vT[0] = bofT; vS[0] = bofS;
    }
    __syncthreads();
    bofT = vT[0]; bofS = vS[0];
    int t = pt[tid] - tv + bofT;
    g_tstart[c] = t;  g_tcur[c] = t;
    g_scur[c] = ps[tid] - sv + bofS;
    g_thist[c] = 0;   g_shist[c] = 0;     // ready for next call
    if (b == 31 && tid == 1023) g_tstart[NCELLS] = N_PTS;
}

// ---------------------------------------------------------------------------
__global__ void scatter_kernel(const float* __restrict__ src,
                               const float* __restrict__ tgt) {
    int gid = blockIdx.x * blockDim.x + threadIdx.x;
    if (gid < N_PTS) {
        float x = tgt[3 * gid], y = tgt[3 * gid + 1], z = tgt[3 * gid + 2];
        bool valid = (x != 0.0f) || (y != 0.0f) || (z != 0.0f);
        float t2 = fmaf(x, x, fmaf(y, y, z * z));
        float4 v;
        if (valid) { v.x = -2.0f * x; v.y = -2.0f * y; v.z = -2.0f * z; v.w = t2; }
        else       { v.x = 0.0f;      v.y = 0.0f;      v.z = 0.0f;      v.w = 1e30f; }
        int c = (cell_coord(z) * NC + cell_coord(y)) * NC + cell_coord(x);
        g_tsort[atomicAdd(&g_tcur[c], 1)] = v;
    } else {
        int i = gid - N_PTS;
        float x = src[3 * i], y = src[3 * i + 1], z = src[3 * i + 2];
        bool valid = (x != 0.0f) || (y != 0.0f) || (z != 0.0f);
        float s2 = fmaf(x, x, fmaf(y, y, z * z));
        float4 v; v.x = x; v.y = y; v.z = z; v.w = valid ? s2 : -1.0f;
        int c = morton3(cell_coord(x), cell_coord(y), cell_coord(z));
        g_ssort[atomicAdd(&g_scur[c], 1)] = v;
    }
}

// Branchless sorted insert, ascending m0..m4 (exact no-op when q >= m4).
__device__ __forceinline__ void insert5(float q, float& m0, float& m1,
                                        float& m2, float& m3, float& m4) {
    float t0 = fminf(m0, q);
    float t1 = fminf(m1, fmaxf(m0, q));
    float t2 = fminf(m2, fmaxf(m1, q));
    float t3 = fminf(m3, fmaxf(m2, q));
    float t4 = fminf(m4, fmaxf(m3, q));
    m0 = t0; m1 = t1; m2 = t2; m3 = t3; m4 = t4;
}

// Warp butterfly merge of 32 per-lane ascending-5 lists -> exact union top-5
// sorted ascending, identical on all lanes. (Validated R4-R10: rel_err = 0.)
__device__ __forceinline__ void warp_merge5(float& a0, float& a1, float& a2,
                                            float& a3, float& a4) {
#pragma unroll
    for (int off = 16; off > 0; off >>= 1) {
        float b0 = __shfl_xor_sync(0xffffffffu, a0, off);
        float b1 = __shfl_xor_sync(0xffffffffu, a1, off);
        float b2 = __shfl_xor_sync(0xffffffffu, a2, off);
        float b3 = __shfl_xor_sync(0xffffffffu, a3, off);
        float b4 = __shfl_xor_sync(0xffffffffu, a4, off);
        float c0 = fminf(a0, b4), c1 = fminf(a1, b3), c2 = fminf(a2, b2);
        float c3 = fminf(a3, b1), c4 = fminf(a4, b0);
        float l04 = fminf(c0, c4), h04 = fmaxf(c0, c4);
        float l13 = fminf(c1, c3), h13 = fmaxf(c1, c3);
        float l2h = fminf(c2, h04), h2h = fmaxf(c2, h04);
        a0 = l04;
        a1 = fminf(l13, l2h); a2 = fmaxf(l13, l2h);
        a3 = fminf(h13, h2h); a4 = fmaxf(h13, h2h);
    }
}

// ---------------------------------------------------------------------------
// Main: one source per warp (strided for balance). Seed (home cell + shells
// until >=5 seen) -> exact union 5th -> tight r2. Sphere pass with
// LANE-PARALLEL row filtering: 32 lanes evaluate 32 candidate rows at once
// (occupancy, y-bound, x-trim, st/en preload), ballot-compact, then only
// surviving rows run the serial candidate loop. r2 refresh once per z-slab.
// ---------------------------------------------------------------------------
__global__ __launch_bounds__(MAIN_THREADS)
void knn_main() {
    __shared__ float red_s[MAIN_WARPS];
    __shared__ int   red_c[MAIN_WARPS];

    const int lane = threadIdx.x & 31;
    const int warp = threadIdx.x >> 5;
    const int sid  = blockIdx.x + warp * MAIN_BLOCKS;    // stride-mix

    const unsigned rw = g_rowmask[lane];
    const unsigned zmask = __ballot_sync(0xffffffffu, rw != 0u);

    float4 sv = g_ssort[sid];
    const float sx = sv.x, sy = sv.y, sz = sv.z;
    const bool  valid = (sv.w >= 0.0f);
    const float s2 = fmaxf(sv.w, 0.0f);

    float m0 = 1e20f, m1 = 1e20f, m2 = 1e20f, m3 = 1e20f, m4 = 1e20f;

    if (valid) {
        const float px = fminf(fmaxf(sx, XMIN), XMAXV);
        const float py = fminf(fmaxf(sy, XMIN), XMAXV);
        const float pz = fminf(fmaxf(sz, XMIN), XMAXV);
        const int ccx = cell_coord(px);
        const int ccy = cell_coord(py);
        const int ccz = cell_coord(pz);

        int seen = 0;

        auto rowbits = [&](int cz) -> unsigned {
            return __shfl_sync(0xffffffffu, rw, cz);
        };
        auto steps = [&](int st, int en) {
            for (int i0 = st; i0 < en; i0 += 32) {
                int i = i0 + lane;
                float4 v = make_float4(0.0f, 0.0f, 0.0f, 1e30f);
                if (i < en) v = g_tsort[i];
                float q = fmaf(sx, v.x, fmaf(sy, v.y, fmaf(sz, v.z, v.w)));
                insert5(q, m0, m1, m2, m3, m4);
            }
        };
        auto span = [&](int cz, int cy, int cxl, int cxr) {
            int base = (cz * NC + cy) * NC;
            int st = g_tstart[base + cxl];
            int en = g_tstart[base + cxr + 1];
            seen += en - st;
            steps(st, en);
        };

        // ---- seed: home cell, then full shells until >=5 candidates seen ----
        if ((rowbits(ccz) >> ccy) & 1u) span(ccz, ccy, ccx, ccx);
        int rs = 0;
        while (seen < KNN && rs < NC) {
            ++rs;
            const int zA = ccz - rs, zB = ccz + rs;
            const int yA = ccy - rs, yB = ccy + rs;
            const int xA = ccx - rs, xB = ccx + rs;
            const int xl = max(xA, 0), xr = min(xB, NC - 1);
            for (int cz = max(zA, 0); cz <= min(zB, NC - 1); ++cz) {
                if (!((zmask >> cz) & 1u)) continue;
                unsigned w32 = rowbits(cz);
                if (!w32) continue;
                if (cz == zA || cz == zB) {           // full z-face
                    for (int cy = max(yA, 0); cy <= min(yB, NC - 1); ++cy)
                        if ((w32 >> cy) & 1u) span(cz, cy, xl, xr);
                } else {
                    if (yA >= 0      && ((w32 >> yA) & 1u)) span(cz, yA, xl, xr);
                    if (yB <= NC - 1 && ((w32 >> yB) & 1u)) span(cz, yB, xl, xr);
                    for (int cy = max(yA + 1, 0); cy <= min(yB - 1, NC - 1); ++cy) {
                        if (!((w32 >> cy) & 1u)) continue;
                        if (xA >= 0)      span(cz, cy, xA, xA);
                        if (xB <= NC - 1) span(cz, cy, xB, xB);
                    }
                }
            }
        }

        // exact union-5th bound from seed (on copies; lane lists intact)
        float r2;
        {
            float a0 = m0, a1 = m1, a2 = m2, a3 = m3, a4 = m4;
            warp_merge5(a0, a1, a2, a3, a4);
            r2 = a4 + s2;
        }

        // ---- sphere pass: lane-parallel row filter, seed-cube exclusion ----
        const int szA = ccz - rs, szB = ccz + rs;
        const int syA = ccy - rs, syB = ccy + rs;
        const int sxA = ccx - rs, sxB = ccx + rs;

        float rmax = sqrtf(r2);
        const int czmin = cell_coord(pz - rmax);
        const int czmax = cell_coord(pz + rmax);

        for (int cz = czmin; cz <= czmax; ++cz) {
            if (!((zmask >> cz) & 1u)) continue;
            float zcmin = XMIN + cz * W;
            float dz = fmaxf(fmaxf(zcmin - pz, pz - (zcmin + W)), 0.0f);
            float dz2 = dz * dz;
            if (dz2 > r2) continue;
            unsigned w32 = rowbits(cz);
            if (!w32) continue;
            float ry = sqrtf(fmaxf(r2 - dz2, 0.0f));
            const int cya = cell_coord(py - ry);
            const int cyb = cell_coord(py + ry);
            const bool zin = (cz >= szA) && (cz <= szB);

            for (int cy0 = cya; cy0 <= cyb; cy0 += 32) {
                const int cy = cy0 + lane;
                bool pred = (cy <= cyb) && (((w32 >> cy) & 1u) != 0u);
                int axl = 0, axr = -1, st = 0, en = 0;
                bool split = false;
                if (pred) {
                    float ycmin = XMIN + cy * W;
                    float dy = fmaxf(fmaxf(ycmin - py, py - (ycmin + W)), 0.0f);
                    float dd = fmaf(dy, dy, dz2);
                    pred = (dd <= r2);
                    if (pred) {
                        float dxm = sqrtf(r2 - dd);
                        axl = cell_coord(px - dxm);
                        axr = cell_coord(px + dxm);
                        split = zin && (cy >= syA) && (cy <= syB);
                        if (!split) {
                            int base = (cz * NC + cy) * NC;
                            st = g_tstart[base + axl];
                            en = g_tstart[base + axr + 1];
                            pred = (en > st);
                        }
                    }
                }
                unsigned bal = __ballot_sync(0xffffffffu, pred);
                while (bal) {
                    int ln = __ffs(bal) - 1;
                    bal &= bal - 1;
                    bool rsplit = __shfl_sync(0xffffffffu, (int)split, ln);
                    if (!rsplit) {
                        int rst = __shfl_sync(0xffffffffu, st, ln);
                        int ren = __shfl_sync(0xffffffffu, en, ln);
                        steps(rst, ren);
                    } else {
                        int raxl = __shfl_sync(0xffffffffu, axl, ln);
                        int raxr = __shfl_sync(0xffffffffu, axr, ln);
                        int rcy  = cy0 + ln;
                        int r1 = min(raxr, sxA - 1);
                        if (raxl <= r1) span(cz, rcy, raxl, r1);
                        int l2 = max(raxl, sxB + 1);
                        if (l2 <= raxr) span(cz, rcy, l2, raxr);
                    }
                }
            }
            // r2 refresh once per z-slab (min over lanes of m4 >= union 5th)
            float mm = m4;
#pragma unroll
            for (int off = 16; off > 0; off >>= 1)
                mm = fminf(mm, __shfl_xor_sync(0xffffffffu, mm, off));
            r2 = fminf(r2, mm + s2);
        }
    }

    // final exact merge + loss contribution
    warp_merge5(m0, m1, m2, m3, m4);
    float wsum = 0.0f; int wcnt = 0;
    if (valid) {
        wsum = sqrtf(fmaxf(m0 + s2, 1e-12f))
             + sqrtf(fmaxf(m1 + s2, 1e-12f))
             + sqrtf(fmaxf(m2 + s2, 1e-12f))
             + sqrtf(fmaxf(m3 + s2, 1e-12f))
             + sqrtf(fmaxf(m4 + s2, 1e-12f));
        wcnt = 1;
    }

    if (lane == 0) { red_s[warp] = wsum; red_c[warp] = wcnt; }
    __syncthreads();
    if (threadIdx.x == 0) {
        float bs = 0.0f; int bc = 0;
#pragma unroll
        for (int w = 0; w < MAIN_WARPS; ++w) { bs += red_s[w]; bc += red_c[w]; }
        g_bsum[blockIdx.x] = bs;
        g_bcnt[blockIdx.x] = bc;
    }
}

// ---------------------------------------------------------------------------
__global__ __launch_bounds__(1024) void finalize_kernel(float* __restrict__ out) {
    __shared__ double ds[1024];
    __shared__ int    di[1024];
    int tid = threadIdx.x;
    double s = 0.0; int c = 0;
#pragma unroll
    for (int j = 0; j < MAIN_BLOCKS / 1024; ++j) {
        int i = j * 1024 + tid;
        s += (double)g_bsum[i];
        c += g_bcnt[i];
    }
    ds[tid] = s; di[tid] = c;
    __syncthreads();
#pragma unroll
    for (int off = 512; off > 0; off >>= 1) {
        if (tid < off) { ds[tid] += ds[tid + off]; di[tid] += di[tid + off]; }
        __syncthreads();
    }
    if (tid == 0) out[0] = (float)(ds[0] / ((double)di[0] * KNN));
    if (tid < 32) g_flag[tid] = 0;    // reset scan lookback flags for next call
}

// ---------------------------------------------------------------------------
extern "C" void kernel_launch(void* const* d_in, const int* in_sizes, int n_in,
                              void* d_out, int out_size) {
    const float* src = (const float*)d_in[0];  // source_pc (2,8192,3)
    const float* tgt = (const float*)d_in[1];  // target_pc (2,8192,3)
    float* out = (float*)d_out;

    hist_kernel<<<2 * N_PTS / 256, 256>>>(src, tgt);     // launch 0
    scan_kernel<<<32, 1024>>>();                         // launch 1
    scatter_kernel<<<2 * N_PTS / 256, 256>>>(src, tgt);  // launch 2
    knn_main<<<MAIN_BLOCKS, MAIN_THREADS>>>();           // launch 3 (profiled)
    finalize_kernel<<<1, 1024>>>(out);                   // launch 4
}